// round 12
// baseline (speedup 1.0000x reference)
#include <cuda_runtime.h>
#include <cuda_bf16.h>
#include <cstdint>

// InterLayerTrajectoryFlow: fused diff -> normalize -> causal 6-tap weighted sum.
// emb: [B, S, D] fp32, S=8192, D=512.
//
// Warp-autonomous design: each warp independently owns a 16-position strip
// and all 512 columns (4 float4 groups per lane). Pass A streams the 22
// needed rows and computes the 21 diff inverse-norms via warp shuffles into
// registers. Pass B re-reads the rows (L1/L2 resident) per column group with
// a sliding 7-row float4 window and applies telescoped 7-tap coefficients.
// ZERO __syncthreads, ZERO shared memory: no barrier phase can ever idle the
// DRAM pipe. Weights come from constant tables (no expf).

#define S_LEN 8192
#define D_DIM 512
#define STRIP 16
#define NDIF  (STRIP + 5)     // 21 diffs per strip
#define SPB   (S_LEN / STRIP) // 512 strips per batch

__constant__ float WT[36] = {
    0.36787944117f, 0.f, 0.f, 0.f, 0.f, 0.f,                                  // w=1
    1.0f, 0.36787944117f, 0.f, 0.f, 0.f, 0.f,                                 // w=2
    1.0f, 0.60653065971f, 0.36787944117f, 0.f, 0.f, 0.f,                      // w=3
    1.0f, 0.71653131057f, 0.51341711903f, 0.36787944117f, 0.f, 0.f,           // w=4
    1.0f, 0.77880078307f, 0.60653065971f, 0.47236655274f, 0.36787944117f, 0.f,// w=5
    1.0f, 0.81873075308f, 0.67032004604f, 0.54881163609f, 0.44932896412f, 0.36787944117f // w=6
};
__constant__ float WSUM[6] = {
    0.36787944117f, 1.36787944117f, 1.97441010088f,
    2.59782787077f, 3.22557744069f, 3.85507084050f
};

__global__ __launch_bounds__(256, 3)
void traj_flow_kernel(const float* __restrict__ emb,
                      const int* __restrict__ layer_idx,
                      float* __restrict__ out) {
    const int lane  = threadIdx.x & 31;
    const int wid   = threadIdx.x >> 5;
    const int wg    = blockIdx.x * 8 + wid;     // global warp id
    const int b     = wg / SPB;
    const int strip = wg % SPB;
    const int pos0  = strip * STRIP;
    const int R0    = pos0 - 6;                 // first row touched (may be <0)
    const long long rowbase = (long long)b * S_LEN;

    const float ds     = 0.1f * (1.0f + (float)(*layer_idx) * 0.8f);
    const float dsinv6 = ds / (WSUM[5] + 1e-8f);
    const bool  fast   = (pos0 >= 6);           // all positions use w=6 window

    const float4* e4 = (const float4*)emb;      // row stride = 128 float4
    const float4 z4  = make_float4(0.f, 0.f, 0.f, 0.f);

    // ================= Pass A: 21 diff inverse-norms into registers =================
    float rv[NDIF];
    {
        float4 p0, p1, p2, p3;
        if (R0 >= 0) {
            const float4* p = e4 + (rowbase + R0) * 128 + lane;
            p0 = p[0]; p1 = p[32]; p2 = p[64]; p3 = p[96];
        } else {
            p0 = z4; p1 = z4; p2 = z4; p3 = z4;
        }
        #pragma unroll
        for (int i = 0; i < NDIF; ++i) {
            const int r = R0 + i + 1;
            float4 c0, c1, c2, c3;
            if (r >= 0) {
                const float4* p = e4 + (rowbase + r) * 128 + lane;
                c0 = p[0]; c1 = p[32]; c2 = p[64]; c3 = p[96];
            } else {
                c0 = z4; c1 = z4; c2 = z4; c3 = z4;
            }
            float s = 0.0f, d;
            d = c0.x - p0.x; s = fmaf(d, d, s);
            d = c0.y - p0.y; s = fmaf(d, d, s);
            d = c0.z - p0.z; s = fmaf(d, d, s);
            d = c0.w - p0.w; s = fmaf(d, d, s);
            d = c1.x - p1.x; s = fmaf(d, d, s);
            d = c1.y - p1.y; s = fmaf(d, d, s);
            d = c1.z - p1.z; s = fmaf(d, d, s);
            d = c1.w - p1.w; s = fmaf(d, d, s);
            d = c2.x - p2.x; s = fmaf(d, d, s);
            d = c2.y - p2.y; s = fmaf(d, d, s);
            d = c2.z - p2.z; s = fmaf(d, d, s);
            d = c2.w - p2.w; s = fmaf(d, d, s);
            d = c3.x - p3.x; s = fmaf(d, d, s);
            d = c3.y - p3.y; s = fmaf(d, d, s);
            d = c3.z - p3.z; s = fmaf(d, d, s);
            d = c3.w - p3.w; s = fmaf(d, d, s);
            s += __shfl_xor_sync(0xffffffffu, s, 16);
            s += __shfl_xor_sync(0xffffffffu, s, 8);
            s += __shfl_xor_sync(0xffffffffu, s, 4);
            s += __shfl_xor_sync(0xffffffffu, s, 2);
            s += __shfl_xor_sync(0xffffffffu, s, 1);
            const float mag = sqrtf(s);
            rv[i] = (mag > 1e-6f) ? (1.0f / (mag + 1e-8f)) : 0.0f;
            p0 = c0; p1 = c1; p2 = c2; p3 = c3;
        }
    }
    if (fast) {
        #pragma unroll
        for (int i = 0; i < NDIF; ++i) rv[i] *= dsinv6;   // fold ds/(wsum+eps)
    }

    // ================= Pass B: sliding window per column group =================
    #pragma unroll 1
    for (int cg = 0; cg < 4; ++cg) {
        const int co = cg * 32 + lane;
        float4 w7[7];
        #pragma unroll
        for (int i = 0; i < 7; ++i) {
            const int r = R0 + i;
            w7[i] = (r >= 0) ? e4[(rowbase + r) * 128 + co] : z4;
        }
        float4* op = (float4*)out + (rowbase + pos0) * 128 + co;

        #pragma unroll
        for (int lp = 0; lp < STRIP; ++lp) {
            float a0, a1, a2, a3, a4, a5, a6;
            if (fast) {
                const float c0 = WT[30] * rv[lp + 5];
                const float c1 = WT[31] * rv[lp + 4];
                const float c2 = WT[32] * rv[lp + 3];
                const float c3 = WT[33] * rv[lp + 2];
                const float c4 = WT[34] * rv[lp + 1];
                const float c5 = WT[35] * rv[lp + 0];
                a0 = c0; a1 = c1 - c0; a2 = c2 - c1; a3 = c3 - c2;
                a4 = c4 - c3; a5 = c5 - c4; a6 = -c5;
            } else {
                const int pos = pos0 + lp;
                float c[6] = {0.f, 0.f, 0.f, 0.f, 0.f, 0.f};
                if (pos >= 1) {
                    const int w = (pos < 6) ? pos : 6;
                    const float inv = ds / (WSUM[w - 1] + 1e-8f);
                    #pragma unroll
                    for (int k = 0; k < 6; ++k)
                        if (k < w)
                            c[k] = WT[(w - 1) * 6 + k] * inv * rv[lp + 5 - k];
                }
                a0 = c[0]; a1 = c[1] - c[0]; a2 = c[2] - c[1]; a3 = c[3] - c[2];
                a4 = c[4] - c[3]; a5 = c[5] - c[4]; a6 = -c[5];
            }
            // out[pos] = sum_j a_j * e[pos-j]; window: w7[i] = row pos-6+i
            float4 acc;
            acc.x = a0 * w7[6].x; acc.y = a0 * w7[6].y;
            acc.z = a0 * w7[6].z; acc.w = a0 * w7[6].w;
            acc.x = fmaf(a1, w7[5].x, acc.x); acc.y = fmaf(a1, w7[5].y, acc.y);
            acc.z = fmaf(a1, w7[5].z, acc.z); acc.w = fmaf(a1, w7[5].w, acc.w);
            acc.x = fmaf(a2, w7[4].x, acc.x); acc.y = fmaf(a2, w7[4].y, acc.y);
            acc.z = fmaf(a2, w7[4].z, acc.z); acc.w = fmaf(a2, w7[4].w, acc.w);
            acc.x = fmaf(a3, w7[3].x, acc.x); acc.y = fmaf(a3, w7[3].y, acc.y);
            acc.z = fmaf(a3, w7[3].z, acc.z); acc.w = fmaf(a3, w7[3].w, acc.w);
            acc.x = fmaf(a4, w7[2].x, acc.x); acc.y = fmaf(a4, w7[2].y, acc.y);
            acc.z = fmaf(a4, w7[2].z, acc.z); acc.w = fmaf(a4, w7[2].w, acc.w);
            acc.x = fmaf(a5, w7[1].x, acc.x); acc.y = fmaf(a5, w7[1].y, acc.y);
            acc.z = fmaf(a5, w7[1].z, acc.z); acc.w = fmaf(a5, w7[1].w, acc.w);
            acc.x = fmaf(a6, w7[0].x, acc.x); acc.y = fmaf(a6, w7[0].y, acc.y);
            acc.z = fmaf(a6, w7[0].z, acc.z); acc.w = fmaf(a6, w7[0].w, acc.w);
            op[lp * 128] = acc;

            #pragma unroll
            for (int i = 0; i < 6; ++i) w7[i] = w7[i + 1];
            if (lp < STRIP - 1)
                w7[6] = e4[(rowbase + R0 + lp + 7) * 128 + co];
        }
    }
}

extern "C" void kernel_launch(void* const* d_in, const int* in_sizes, int n_in,
                              void* d_out, int out_size) {
    const float* emb = (const float*)d_in[0];
    const int* layer_idx = (const int*)d_in[1];
    float* out = (float*)d_out;

    const int B = in_sizes[0] / (S_LEN * D_DIM);
    const int nwarps = B * SPB;            // one warp per 16-position strip
    const int nblocks = nwarps / 8;        // 256 threads = 8 warps per block

    traj_flow_kernel<<<nblocks, 256>>>(emb, layer_idx, out);
}

// round 14
// speedup vs baseline: 1.7313x; 1.7313x over previous
#include <cuda_runtime.h>
#include <cuda_bf16.h>
#include <cstdint>

// InterLayerTrajectoryFlow: fused diff -> normalize -> causal 6-tap weighted sum.
// emb: [B, S, D] fp32, S=8192, D=512.
//
// Single-barrier design: block = 256 threads, 32-position chunk, 38-row fp32
// tile in smem (76KB, 2 blocks/SM, regs free to 128 -> no spills).
//  Load phase: warp w owns 6 rows (one overlaps next warp), 24 LDG.128/thread
//    with high MLP, stores 5 rows to the tile, computes its 5 diff-norms
//    inline via 5-stage warp shuffles -> srinv in smem.
//  ONE __syncthreads.
//  Store phase: thread = (col-group, 16-position half); 21 srinv values
//    loaded once into registers (broadcast LDS), sliding 7xfloat4 window,
//    telescoped 7-tap coefficients computed in registers, 16 STG.128.
// DRAM busy in both phases (loads then store-drain); no global re-read.
//
// (Resubmission: R13 hit a broker/container failure before execution.
// Source re-audited for compile validity after the R10 lesson; no defect
// found. Design remains unmeasured, not refuted.)

#define S_LEN 8192
#define D_DIM 512
#define PC    32
#define ROWS  38              // PC + 6
#define NDIFF 37              // PC + 5

#define TILE_F  (ROWS * D_DIM)          // 19456 floats
#define SRINV_OFF TILE_F
#define SMEM_F  (TILE_F + NDIFF + 3)
#define SMEM_BYTES (SMEM_F * 4)

// exp(-k/5) weights for the full w=6 window
#define W60 1.0f
#define W61 0.81873075308f
#define W62 0.67032004604f
#define W63 0.54881163609f
#define W64 0.44932896412f
#define W65 0.36787944117f
#define WSUM6 3.85507084050f

__constant__ float WT[36] = {
    0.36787944117f, 0.f, 0.f, 0.f, 0.f, 0.f,                                  // w=1
    1.0f, 0.36787944117f, 0.f, 0.f, 0.f, 0.f,                                 // w=2
    1.0f, 0.60653065971f, 0.36787944117f, 0.f, 0.f, 0.f,                      // w=3
    1.0f, 0.71653131057f, 0.51341711903f, 0.36787944117f, 0.f, 0.f,           // w=4
    1.0f, 0.77880078307f, 0.60653065971f, 0.47236655274f, 0.36787944117f, 0.f,// w=5
    1.0f, 0.81873075308f, 0.67032004604f, 0.54881163609f, 0.44932896412f, 0.36787944117f // w=6
};
__constant__ float WSUM[6] = {
    0.36787944117f, 1.36787944117f, 1.97441010088f,
    2.59782787077f, 3.22557744069f, 3.85507084050f
};

__global__ __launch_bounds__(256, 2)
void traj_flow_kernel(const float* __restrict__ emb,
                      const int* __restrict__ layer_idx,
                      float* __restrict__ out) {
    extern __shared__ float sm[];
    float4* tile4 = (float4*)sm;               // [ROWS][128] float4
    float*  srinv = sm + SRINV_OFF;            // [NDIFF]

    const int tid  = threadIdx.x;
    const int lane = tid & 31;
    const int wid  = tid >> 5;                 // warp 0..7
    const int b    = blockIdx.y;
    const int pos0 = blockIdx.x * PC;
    const int R0   = pos0 - 6;                 // global row of tile row 0
    const long long rowbase = (long long)b * S_LEN;

    const float ds     = 0.1f * (1.0f + (float)(*layer_idx) * 0.8f);
    const float dsinv6 = ds / (WSUM6 + 1e-8f);

    const float4* e4 = (const float4*)emb;     // row stride = 128 float4
    const float4  z4 = make_float4(0.f, 0.f, 0.f, 0.f);

    // ================= Load phase: warp w -> rows 5w..5w+5 =================
    {
        const int rw     = wid * 5;            // first tile row of this warp
        const int nrows  = (wid < 7) ? 6 : 3;  // warp 7: rows 35,36,37
        const int nstore = (wid < 7) ? 5 : 3;

        float4 p0 = z4, p1 = z4, p2 = z4, p3 = z4;
        #pragma unroll
        for (int i = 0; i < 6; ++i) {
            if (i < nrows) {
                const int tr = rw + i;
                const int g  = R0 + tr;
                float4 c0, c1, c2, c3;
                if (g >= 0) {
                    const float4* p = e4 + (rowbase + g) * 128 + lane;
                    c0 = p[0]; c1 = p[32]; c2 = p[64]; c3 = p[96];
                } else {
                    c0 = z4; c1 = z4; c2 = z4; c3 = z4;
                }
                if (i < nstore) {
                    tile4[tr * 128 + lane]      = c0;
                    tile4[tr * 128 + lane + 32] = c1;
                    tile4[tr * 128 + lane + 64] = c2;
                    tile4[tr * 128 + lane + 96] = c3;
                }
                if (i > 0) {
                    float s = 0.0f, d;
                    d = c0.x - p0.x; s = fmaf(d, d, s);
                    d = c0.y - p0.y; s = fmaf(d, d, s);
                    d = c0.z - p0.z; s = fmaf(d, d, s);
                    d = c0.w - p0.w; s = fmaf(d, d, s);
                    d = c1.x - p1.x; s = fmaf(d, d, s);
                    d = c1.y - p1.y; s = fmaf(d, d, s);
                    d = c1.z - p1.z; s = fmaf(d, d, s);
                    d = c1.w - p1.w; s = fmaf(d, d, s);
                    d = c2.x - p2.x; s = fmaf(d, d, s);
                    d = c2.y - p2.y; s = fmaf(d, d, s);
                    d = c2.z - p2.z; s = fmaf(d, d, s);
                    d = c2.w - p2.w; s = fmaf(d, d, s);
                    d = c3.x - p3.x; s = fmaf(d, d, s);
                    d = c3.y - p3.y; s = fmaf(d, d, s);
                    d = c3.z - p3.z; s = fmaf(d, d, s);
                    d = c3.w - p3.w; s = fmaf(d, d, s);
                    s += __shfl_xor_sync(0xffffffffu, s, 16);
                    s += __shfl_xor_sync(0xffffffffu, s, 8);
                    s += __shfl_xor_sync(0xffffffffu, s, 4);
                    s += __shfl_xor_sync(0xffffffffu, s, 2);
                    s += __shfl_xor_sync(0xffffffffu, s, 1);
                    if (lane == 0) {
                        const float mag = sqrtf(s);
                        srinv[tr - 1] = (mag > 1e-6f) ? (1.0f / (mag + 1e-8f)) : 0.0f;
                    }
                }
                p0 = c0; p1 = c1; p2 = c2; p3 = c3;
            }
        }
    }
    __syncthreads();   // the ONLY barrier

    // ================= Store phase: (col-group, 16-position half) =================
    {
        const int cg  = tid & 127;             // column group 0..127
        const int h   = tid >> 7;              // 0..1
        const int lp0 = h * 16;                // first local position

        // srinv values needed: indices lp0 .. lp0+20 (lp+5-k, lp in [lp0,lp0+15])
        float rvl[21];
        #pragma unroll
        for (int m = 0; m < 21; ++m) rvl[m] = srinv[lp0 + m];

        const bool fastall = (pos0 + lp0) >= 6;  // all 16 positions use w=6
        if (fastall) {
            #pragma unroll
            for (int m = 0; m < 21; ++m) rvl[m] *= dsinv6;
        }

        float4 w7[7];
        #pragma unroll
        for (int i = 0; i < 7; ++i)
            w7[i] = tile4[(lp0 + i) * 128 + cg];

        float4* op = (float4*)out + (rowbase + pos0 + lp0) * 128 + cg;

        #pragma unroll
        for (int q = 0; q < 16; ++q) {
            float a0, a1, a2, a3, a4, a5, a6;
            if (fastall) {
                const float c0 = W60 * rvl[q + 5];
                const float c1 = W61 * rvl[q + 4];
                const float c2 = W62 * rvl[q + 3];
                const float c3 = W63 * rvl[q + 2];
                const float c4 = W64 * rvl[q + 1];
                const float c5 = W65 * rvl[q + 0];
                a0 = c0; a1 = c1 - c0; a2 = c2 - c1; a3 = c3 - c2;
                a4 = c4 - c3; a5 = c5 - c4; a6 = -c5;
            } else {
                const int pos = pos0 + lp0 + q;
                float c[6] = {0.f, 0.f, 0.f, 0.f, 0.f, 0.f};
                if (pos >= 1) {
                    const int w = (pos < 6) ? pos : 6;
                    const float inv = ds / (WSUM[w - 1] + 1e-8f);
                    #pragma unroll
                    for (int k = 0; k < 6; ++k)
                        if (k < w)
                            c[k] = WT[(w - 1) * 6 + k] * inv * rvl[q + 5 - k];
                }
                a0 = c[0]; a1 = c[1] - c[0]; a2 = c[2] - c[1]; a3 = c[3] - c[2];
                a4 = c[4] - c[3]; a5 = c[5] - c[4]; a6 = -c[5];
            }
            // out[pos] = sum_j a_j * e[pos-j]; w7[i] = row (pos-6+i)
            float4 acc;
            acc.x = a0 * w7[6].x; acc.y = a0 * w7[6].y;
            acc.z = a0 * w7[6].z; acc.w = a0 * w7[6].w;
            acc.x = fmaf(a1, w7[5].x, acc.x); acc.y = fmaf(a1, w7[5].y, acc.y);
            acc.z = fmaf(a1, w7[5].z, acc.z); acc.w = fmaf(a1, w7[5].w, acc.w);
            acc.x = fmaf(a2, w7[4].x, acc.x); acc.y = fmaf(a2, w7[4].y, acc.y);
            acc.z = fmaf(a2, w7[4].z, acc.z); acc.w = fmaf(a2, w7[4].w, acc.w);
            acc.x = fmaf(a3, w7[3].x, acc.x); acc.y = fmaf(a3, w7[3].y, acc.y);
            acc.z = fmaf(a3, w7[3].z, acc.z); acc.w = fmaf(a3, w7[3].w, acc.w);
            acc.x = fmaf(a4, w7[2].x, acc.x); acc.y = fmaf(a4, w7[2].y, acc.y);
            acc.z = fmaf(a4, w7[2].z, acc.z); acc.w = fmaf(a4, w7[2].w, acc.w);
            acc.x = fmaf(a5, w7[1].x, acc.x); acc.y = fmaf(a5, w7[1].y, acc.y);
            acc.z = fmaf(a5, w7[1].z, acc.z); acc.w = fmaf(a5, w7[1].w, acc.w);
            acc.x = fmaf(a6, w7[0].x, acc.x); acc.y = fmaf(a6, w7[0].y, acc.y);
            acc.z = fmaf(a6, w7[0].z, acc.z); acc.w = fmaf(a6, w7[0].w, acc.w);
            op[q * 128] = acc;

            #pragma unroll
            for (int i = 0; i < 6; ++i) w7[i] = w7[i + 1];
            if (q < 15)
                w7[6] = tile4[(lp0 + q + 7) * 128 + cg];
        }
    }
}

extern "C" void kernel_launch(void* const* d_in, const int* in_sizes, int n_in,
                              void* d_out, int out_size) {
    const float* emb = (const float*)d_in[0];
    const int* layer_idx = (const int*)d_in[1];
    float* out = (float*)d_out;

    const int B = in_sizes[0] / (S_LEN * D_DIM);

    cudaFuncSetAttribute(traj_flow_kernel,
                         cudaFuncAttributeMaxDynamicSharedMemorySize, SMEM_BYTES);

    dim3 grid(S_LEN / PC, B);
    traj_flow_kernel<<<grid, 256, SMEM_BYTES>>>(emb, layer_idx, out);
}

// round 15
// speedup vs baseline: 2.0081x; 1.1599x over previous
#include <cuda_runtime.h>
#include <cuda_bf16.h>
#include <cstdint>

// InterLayerTrajectoryFlow: fused diff -> normalize -> causal 6-tap weighted sum.
// emb: [B, S, D] fp32, S=8192, D=512.
//
// Single-barrier design, doubled warps: block = 512 threads, 32-position
// chunk, 38-row fp32 tile in smem (76KB, 2 blocks/SM -> 32 warps/SM).
//  Load phase: 16 warps split 38 rows (warps 0-4: 4 rows/3 diffs,
//    warps 5-15: 3 rows/2 diffs), ~12-16 LDG.128/thread, diff-norms inline
//    via 5-stage warp shuffles -> srinv in smem.
//  ONE __syncthreads.
//  Store phase: thread = (col-group, 8-position quarter); 13 srinv values in
//    registers, sliding 7xfloat4 window, telescoped 7-tap coeffs, 8 STG.128.

#define S_LEN 8192
#define D_DIM 512
#define PC    32
#define ROWS  38              // PC + 6
#define NDIFF 37              // PC + 5

#define TILE_F  (ROWS * D_DIM)          // 19456 floats
#define SRINV_OFF TILE_F
#define SMEM_F  (TILE_F + NDIFF + 3)
#define SMEM_BYTES (SMEM_F * 4)

// exp(-k/5) weights for the full w=6 window
#define W60 1.0f
#define W61 0.81873075308f
#define W62 0.67032004604f
#define W63 0.54881163609f
#define W64 0.44932896412f
#define W65 0.36787944117f
#define WSUM6 3.85507084050f

__constant__ float WT[36] = {
    0.36787944117f, 0.f, 0.f, 0.f, 0.f, 0.f,                                  // w=1
    1.0f, 0.36787944117f, 0.f, 0.f, 0.f, 0.f,                                 // w=2
    1.0f, 0.60653065971f, 0.36787944117f, 0.f, 0.f, 0.f,                      // w=3
    1.0f, 0.71653131057f, 0.51341711903f, 0.36787944117f, 0.f, 0.f,           // w=4
    1.0f, 0.77880078307f, 0.60653065971f, 0.47236655274f, 0.36787944117f, 0.f,// w=5
    1.0f, 0.81873075308f, 0.67032004604f, 0.54881163609f, 0.44932896412f, 0.36787944117f // w=6
};
__constant__ float WSUM[6] = {
    0.36787944117f, 1.36787944117f, 1.97441010088f,
    2.59782787077f, 3.22557744069f, 3.85507084050f
};

__global__ __launch_bounds__(512, 2)
void traj_flow_kernel(const float* __restrict__ emb,
                      const int* __restrict__ layer_idx,
                      float* __restrict__ out) {
    extern __shared__ float sm[];
    float4* tile4 = (float4*)sm;               // [ROWS][128] float4
    float*  srinv = sm + SRINV_OFF;            // [NDIFF]

    const int tid  = threadIdx.x;
    const int lane = tid & 31;
    const int wid  = tid >> 5;                 // warp 0..15
    const int b    = blockIdx.y;
    const int pos0 = blockIdx.x * PC;
    const int R0   = pos0 - 6;                 // global row of tile row 0
    const long long rowbase = (long long)b * S_LEN;

    const float ds     = 0.1f * (1.0f + (float)(*layer_idx) * 0.8f);
    const float dsinv6 = ds / (WSUM6 + 1e-8f);

    const float4* e4 = (const float4*)emb;     // row stride = 128 float4
    const float4  z4 = make_float4(0.f, 0.f, 0.f, 0.f);

    // ========== Load phase: 16 warps over 38 rows / 37 diffs ==========
    {
        // warps 0-4: diffs 3w..3w+2 (3 diffs, 4 rows); warps 5-15: 2 diffs, 3 rows
        int d0, nd;
        if (wid < 5) { d0 = 3 * wid;            nd = 3; }
        else         { d0 = 15 + 2 * (wid - 5); nd = 2; }
        // loads rows d0..d0+nd; stores rows d0..d0+nd-1 (warp 15 also row 37)

        float4 p0 = z4, p1 = z4, p2 = z4, p3 = z4;
        #pragma unroll
        for (int i = 0; i < 4; ++i) {
            if (i <= nd) {
                const int tr = d0 + i;
                const int g  = R0 + tr;
                float4 c0, c1, c2, c3;
                if (g >= 0) {
                    const float4* p = e4 + (rowbase + g) * 128 + lane;
                    c0 = p[0]; c1 = p[32]; c2 = p[64]; c3 = p[96];
                } else {
                    c0 = z4; c1 = z4; c2 = z4; c3 = z4;
                }
                if (i < nd || wid == 15) {
                    tile4[tr * 128 + lane]      = c0;
                    tile4[tr * 128 + lane + 32] = c1;
                    tile4[tr * 128 + lane + 64] = c2;
                    tile4[tr * 128 + lane + 96] = c3;
                }
                if (i > 0) {
                    float s = 0.0f, d;
                    d = c0.x - p0.x; s = fmaf(d, d, s);
                    d = c0.y - p0.y; s = fmaf(d, d, s);
                    d = c0.z - p0.z; s = fmaf(d, d, s);
                    d = c0.w - p0.w; s = fmaf(d, d, s);
                    d = c1.x - p1.x; s = fmaf(d, d, s);
                    d = c1.y - p1.y; s = fmaf(d, d, s);
                    d = c1.z - p1.z; s = fmaf(d, d, s);
                    d = c1.w - p1.w; s = fmaf(d, d, s);
                    d = c2.x - p2.x; s = fmaf(d, d, s);
                    d = c2.y - p2.y; s = fmaf(d, d, s);
                    d = c2.z - p2.z; s = fmaf(d, d, s);
                    d = c2.w - p2.w; s = fmaf(d, d, s);
                    d = c3.x - p3.x; s = fmaf(d, d, s);
                    d = c3.y - p3.y; s = fmaf(d, d, s);
                    d = c3.z - p3.z; s = fmaf(d, d, s);
                    d = c3.w - p3.w; s = fmaf(d, d, s);
                    s += __shfl_xor_sync(0xffffffffu, s, 16);
                    s += __shfl_xor_sync(0xffffffffu, s, 8);
                    s += __shfl_xor_sync(0xffffffffu, s, 4);
                    s += __shfl_xor_sync(0xffffffffu, s, 2);
                    s += __shfl_xor_sync(0xffffffffu, s, 1);
                    if (lane == 0) {
                        const float mag = sqrtf(s);
                        srinv[tr - 1] = (mag > 1e-6f) ? (1.0f / (mag + 1e-8f)) : 0.0f;
                    }
                }
                p0 = c0; p1 = c1; p2 = c2; p3 = c3;
            }
        }
    }
    __syncthreads();   // the ONLY barrier

    // ========== Store phase: (col-group, 8-position quarter) ==========
    {
        const int cg  = tid & 127;             // column group 0..127
        const int qt  = tid >> 7;              // 0..3
        const int lp0 = qt * 8;                // first local position

        // srinv indices needed: lp0 .. lp0+12
        float rvl[13];
        #pragma unroll
        for (int m = 0; m < 13; ++m) rvl[m] = srinv[lp0 + m];

        const bool fastall = (pos0 + lp0) >= 6;  // all 8 positions use w=6
        if (fastall) {
            #pragma unroll
            for (int m = 0; m < 13; ++m) rvl[m] *= dsinv6;
        }

        float4 w7[7];
        #pragma unroll
        for (int i = 0; i < 7; ++i)
            w7[i] = tile4[(lp0 + i) * 128 + cg];

        float4* op = (float4*)out + (rowbase + pos0 + lp0) * 128 + cg;

        #pragma unroll
        for (int q = 0; q < 8; ++q) {
            float a0, a1, a2, a3, a4, a5, a6;
            if (fastall) {
                const float c0 = W60 * rvl[q + 5];
                const float c1 = W61 * rvl[q + 4];
                const float c2 = W62 * rvl[q + 3];
                const float c3 = W63 * rvl[q + 2];
                const float c4 = W64 * rvl[q + 1];
                const float c5 = W65 * rvl[q + 0];
                a0 = c0; a1 = c1 - c0; a2 = c2 - c1; a3 = c3 - c2;
                a4 = c4 - c3; a5 = c5 - c4; a6 = -c5;
            } else {
                const int pos = pos0 + lp0 + q;
                float c[6] = {0.f, 0.f, 0.f, 0.f, 0.f, 0.f};
                if (pos >= 1) {
                    const int w = (pos < 6) ? pos : 6;
                    const float inv = ds / (WSUM[w - 1] + 1e-8f);
                    #pragma unroll
                    for (int k = 0; k < 6; ++k)
                        if (k < w)
                            c[k] = WT[(w - 1) * 6 + k] * inv * rvl[q + 5 - k];
                }
                a0 = c[0]; a1 = c[1] - c[0]; a2 = c[2] - c[1]; a3 = c[3] - c[2];
                a4 = c[4] - c[3]; a5 = c[5] - c[4]; a6 = -c[5];
            }
            // out[pos] = sum_j a_j * e[pos-j]; w7[i] = row (pos-6+i)
            float4 acc;
            acc.x = a0 * w7[6].x; acc.y = a0 * w7[6].y;
            acc.z = a0 * w7[6].z; acc.w = a0 * w7[6].w;
            acc.x = fmaf(a1, w7[5].x, acc.x); acc.y = fmaf(a1, w7[5].y, acc.y);
            acc.z = fmaf(a1, w7[5].z, acc.z); acc.w = fmaf(a1, w7[5].w, acc.w);
            acc.x = fmaf(a2, w7[4].x, acc.x); acc.y = fmaf(a2, w7[4].y, acc.y);
            acc.z = fmaf(a2, w7[4].z, acc.z); acc.w = fmaf(a2, w7[4].w, acc.w);
            acc.x = fmaf(a3, w7[3].x, acc.x); acc.y = fmaf(a3, w7[3].y, acc.y);
            acc.z = fmaf(a3, w7[3].z, acc.z); acc.w = fmaf(a3, w7[3].w, acc.w);
            acc.x = fmaf(a4, w7[2].x, acc.x); acc.y = fmaf(a4, w7[2].y, acc.y);
            acc.z = fmaf(a4, w7[2].z, acc.z); acc.w = fmaf(a4, w7[2].w, acc.w);
            acc.x = fmaf(a5, w7[1].x, acc.x); acc.y = fmaf(a5, w7[1].y, acc.y);
            acc.z = fmaf(a5, w7[1].z, acc.z); acc.w = fmaf(a5, w7[1].w, acc.w);
            acc.x = fmaf(a6, w7[0].x, acc.x); acc.y = fmaf(a6, w7[0].y, acc.y);
            acc.z = fmaf(a6, w7[0].z, acc.z); acc.w = fmaf(a6, w7[0].w, acc.w);
            op[q * 128] = acc;

            #pragma unroll
            for (int i = 0; i < 6; ++i) w7[i] = w7[i + 1];
            if (q < 7)
                w7[6] = tile4[(lp0 + q + 7) * 128 + cg];
        }
    }
}

extern "C" void kernel_launch(void* const* d_in, const int* in_sizes, int n_in,
                              void* d_out, int out_size) {
    const float* emb = (const float*)d_in[0];
    const int* layer_idx = (const int*)d_in[1];
    float* out = (float*)d_out;

    const int B = in_sizes[0] / (S_LEN * D_DIM);

    cudaFuncSetAttribute(traj_flow_kernel,
                         cudaFuncAttributeMaxDynamicSharedMemorySize, SMEM_BYTES);

    dim3 grid(S_LEN / PC, B);
    traj_flow_kernel<<<grid, 512, SMEM_BYTES>>>(emb, layer_idx, out);
}